// round 16
// baseline (speedup 1.0000x reference)
#include <cuda_runtime.h>
#include <math.h>
#include <stdint.h>

#define SEQL 256
#define BATCH 64
#define HID 1024
#define GATES 4096
#define MROWS (SEQL*BATCH)      // 16384
#define BH (BATCH*HID)          // 65536

// ---------------- scratch (device globals; no cudaMalloc allowed) ----------
__device__ float g_xp[(size_t)MROWS * GATES];   // 256 MB: x-projection for one layer
__device__ float g_ys[(size_t)SEQL * BH];       // 64 MB: layer-0 h history
__device__ float g_hb[2 * BH];                  // layer-1 h ping-pong
__device__ volatile unsigned g_bar_gen;
__device__ unsigned g_cnt_grp[8];
__device__ unsigned g_cnt_root;
__device__ volatile unsigned g_flag[128 * 32];  // per-block step flags, 128B padded

// ---------------- helpers ---------------------------------------------------
__device__ __forceinline__ uint32_t f2tf32(float x) {
    uint32_t r; asm("cvt.rna.tf32.f32 %0, %1;" : "=r"(r) : "f"(x)); return r;
}
__device__ __forceinline__ void mma8(float* d, const uint32_t* a, const uint32_t* b) {
    asm volatile(
        "mma.sync.aligned.m16n8k8.row.col.f32.tf32.tf32.f32 "
        "{%0,%1,%2,%3},{%4,%5,%6,%7},{%8,%9},{%0,%1,%2,%3};"
        : "+f"(d[0]), "+f"(d[1]), "+f"(d[2]), "+f"(d[3])
        : "r"(a[0]), "r"(a[1]), "r"(a[2]), "r"(a[3]), "r"(b[0]), "r"(b[1]));
}
__device__ __forceinline__ void cpa16(uint32_t s, const void* g) {
    asm volatile("cp.async.cg.shared.global [%0], [%1], 16;" :: "r"(s), "l"(g));
}
#define CP_COMMIT() asm volatile("cp.async.commit_group;")
#define CP_WAIT(n)  asm volatile("cp.async.wait_group %0;" :: "n"(n))

__device__ __forceinline__ float sigf(float x) { return __fdividef(1.f, 1.f + __expf(-x)); }
__device__ __forceinline__ float tanhfast(float x) { return __fdividef(2.f, 1.f + __expf(-2.f * x)) - 1.f; }

// ---------------- hierarchical grid barrier (startup only) ------------------
__device__ __forceinline__ unsigned gridbar_arrive() {
    __threadfence();
    __syncthreads();
    unsigned gen = 0;
    if (threadIdx.x == 0) {
        gen = g_bar_gen;
        unsigned grp = blockIdx.x & 7u;
        if (atomicAdd(&g_cnt_grp[grp], 1u) == 15u) {
            atomicExch(&g_cnt_grp[grp], 0u);
            if (atomicAdd(&g_cnt_root, 1u) == 7u) {
                atomicExch(&g_cnt_root, 0u);
                __threadfence();
                g_bar_gen = gen + 1u;
            }
        }
    }
    return gen;
}
__device__ __forceinline__ void gridbar_wait(unsigned gen) {
    if (threadIdx.x == 0) {
        while (g_bar_gen == gen) { __nanosleep(16); }
        __threadfence();
    }
    __syncthreads();
}

// ---------------- tf32 SGEMM: cp.async 2-stage pipelined (unchanged R3) -----
#define STG 8192   // floats per stage (As 4096 + Ws 4096)
__global__ __launch_bounds__(256, 2) void sgemm_xp(
    const float* __restrict__ A, const int* __restrict__ gidx,
    const float* __restrict__ W,
    const float* __restrict__ b1, const float* __restrict__ b2,
    float* __restrict__ C)
{
    extern __shared__ float smf[];
    const uint32_t smem_b = (uint32_t)__cvta_generic_to_shared(smf);
    const int bn = blockIdx.x * 128;
    const int bm = blockIdx.y * 128;
    const int tid = threadIdx.x;
    const int warp = tid >> 5, lane = tid & 31;
    const int g = lane >> 2, tig = lane & 3;
    const int wm = warp >> 2, wn = warp & 3;

    int cm[4]; int cj[4]; int arow[4]; uint32_t adst[4], wdst[4];
#pragma unroll
    for (int rep = 0; rep < 4; rep++) {
        int q = tid + rep * 256;
        int m = q >> 3, j = q & 7;
        cm[rep] = m; cj[rep] = j;
        arow[rep] = gidx ? gidx[bm + m] : (bm + m);
        uint32_t off = (uint32_t)(m * 32 + ((4 * j) ^ ((m & 7) << 2)));
        adst[rep] = smem_b + off * 4;
        wdst[rep] = smem_b + (off + 4096) * 4;
    }

    float acc[4][4][4];
#pragma unroll
    for (int mi = 0; mi < 4; mi++)
#pragma unroll
        for (int ni = 0; ni < 4; ni++)
#pragma unroll
            for (int r = 0; r < 4; r++) acc[mi][ni][r] = 0.f;

#pragma unroll
    for (int rep = 0; rep < 4; rep++) {
        cpa16(adst[rep], A + (size_t)arow[rep] * 1024 + 4 * cj[rep]);
        cpa16(wdst[rep], W + (size_t)(bn + cm[rep]) * 1024 + 4 * cj[rep]);
    }
    CP_COMMIT();

    const int swz = g << 2;
    for (int c = 0; c < 32; c++) {
        if (c + 1 < 32) {
            uint32_t so = (uint32_t)(((c + 1) & 1) * STG) * 4;
            int kc = (c + 1) * 32;
#pragma unroll
            for (int rep = 0; rep < 4; rep++) {
                cpa16(adst[rep] + so, A + (size_t)arow[rep] * 1024 + kc + 4 * cj[rep]);
                cpa16(wdst[rep] + so, W + (size_t)(bn + cm[rep]) * 1024 + kc + 4 * cj[rep]);
            }
        }
        CP_COMMIT();
        CP_WAIT(1);
        __syncthreads();

        const float* As = smf + (c & 1) * STG;
        const float* Ws = As + 4096;
#pragma unroll
        for (int kk = 0; kk < 4; kk++) {
            int kl = (kk * 8 + tig) ^ swz;
            int kh = (kk * 8 + tig + 4) ^ swz;
            uint32_t a[4][4], b[4][2];
#pragma unroll
            for (int mi = 0; mi < 4; mi++) {
                int base = (wm * 64 + mi * 16 + g) * 32;
                a[mi][0] = f2tf32(As[base + kl]);
                a[mi][1] = f2tf32(As[base + 256 + kl]);
                a[mi][2] = f2tf32(As[base + kh]);
                a[mi][3] = f2tf32(As[base + 256 + kh]);
            }
#pragma unroll
            for (int ni = 0; ni < 4; ni++) {
                int nb = (wn * 32 + ni * 8 + g) * 32;
                b[ni][0] = f2tf32(Ws[nb + kl]);
                b[ni][1] = f2tf32(Ws[nb + kh]);
            }
#pragma unroll
            for (int mi = 0; mi < 4; mi++)
#pragma unroll
                for (int ni = 0; ni < 4; ni++)
                    mma8(acc[mi][ni], a[mi], b[ni]);
        }
        __syncthreads();
    }

#pragma unroll
    for (int ni = 0; ni < 4; ni++) {
        int nc = bn + wn * 32 + ni * 8 + 2 * tig;
        float bia0 = b1[nc] + b2[nc];
        float bia1 = b1[nc + 1] + b2[nc + 1];
#pragma unroll
        for (int mi = 0; mi < 4; mi++) {
            int mr = bm + wm * 64 + mi * 16 + g;
            *(float2*)(C + (size_t)mr * GATES + nc) =
                make_float2(acc[mi][ni][0] + bia0, acc[mi][ni][1] + bia1);
            *(float2*)(C + (size_t)(mr + 8) * GATES + nc) =
                make_float2(acc[mi][ni][2] + bia0, acc[mi][ni][3] + bia1);
        }
    }
}
#define SGEMM_SMEM (2 * STG * 4)

// ---------------- persistent LSTM recurrence v12 -----------------------------
// 128 blocks x 256 threads (8 warps). Block owns 8 hidden cols (32 gate cols).
// Warp = (kq = warp&3: 256-k quarter, bhh = warp>>2: 32 batch rows, mi=2).
// Weights read 2x per block per step (was 4x in R13/R15) -> b-frag LDS halved,
// h still read exactly once. Same 16-chunk x 16k depth-2 warp-private
// pipeline, same 1-sync reduction shape, R15 poller-mirror + early publish.
#define PW2 36
#define HPAD 20
#define NCH 16
#define CH_F (32 * HPAD)                        // 640 floats per chunk buffer
#define HS_OFF  (1024 * PW2)                    // 36864
#define RED_OFF (HS_OFF + 8 * 2 * CH_F)         // 47104
#define SFL_OFF (RED_OFF + 6 * 32 * 32)         // 53248
#define REC_SMEM ((SFL_OFF + 32) * 4)           // 213,120 B

__global__ __launch_bounds__(256, 1) void lstm_rec(
    const float* __restrict__ xp, const float* __restrict__ whh,
    float* hist, int mode, float* __restrict__ out_h, float* __restrict__ out_c)
{
    extern __shared__ float sm[];
    uint32_t* ws2 = (uint32_t*)sm;             // [1024][PW2] tf32
    float* red = sm + RED_OFF;                 // [6][32 idx][32 lane]
    volatile unsigned* sfl = (volatile unsigned*)(sm + SFL_OFF);  // [4] mirrors x8 pad

    const int tid  = threadIdx.x;
    const int warp = tid >> 5, lane = tid & 31;
    const int g = lane >> 2, tig = lane & 3;
    const int kq  = warp & 3;                  // k-quarter (256 k)
    const int bhh = warp >> 2;                 // batch half (32 rows)
    const int j0 = blockIdx.x * 8;
    const int rot = blockIdx.x & 15;           // chunk-order stagger

    if (tid == 0) g_flag[blockIdx.x * 32] = 0u;
    if (tid < 4) sfl[tid * 8] = 0u;

    // warp-private double buffer (32 rows x HPAD floats per chunk)
    float* buf0 = sm + HS_OFF + warp * 2 * CH_F;
    float* buf1 = buf0 + CH_F;
    const uint32_t b0_u32 = (uint32_t)__cvta_generic_to_shared(buf0);
    const uint32_t b1_u32 = b0_u32 + CH_F * 4;

    // staging: lane stages its row (bhh*32+lane), one 16k chunk = 4 cpa16
    const uint32_t sdst0 = b0_u32 + (uint32_t)(lane * HPAD) * 4;
    const uint32_t sdst1 = b1_u32 + (uint32_t)(lane * HPAD) * 4;

    // preload weights: ws2[k][c], c = j*4 + gate (256 threads)
    {
        int c   = tid & 31;                    // j = c>>2, gate = c&3
        int kq2 = tid >> 5;                    // 0..7, 128 k each
        int wrow = ((c & 3) << 10) + j0 + (c >> 2);
        const float4* w4 = (const float4*)(whh + (size_t)wrow * 1024);
        for (int k4 = kq2 * 32; k4 < kq2 * 32 + 32; k4++) {
            float4 v = w4[k4];
            int k = 4 * k4;
            ws2[(k+0)*PW2 + c] = f2tf32(v.x);
            ws2[(k+1)*PW2 + c] = f2tf32(v.y);
            ws2[(k+2)*PW2 + c] = f2tf32(v.z);
            ws2[(k+3)*PW2 + c] = f2tf32(v.w);
        }
    }
    // startup barrier: flag resets + weight preloads globally done
    gridbar_wait(gridbar_arrive());

    float cst[8];
#pragma unroll
    for (int i = 0; i < 8; i++) cst[i] = 0.f;
    const int khb = kq * 256;
    // poller warps (bhh==0, warps 0-3): one flag per lane, blocks [32kq..+32)
    const volatile unsigned* myflag = &g_flag[(kq * 32 + lane) * 32];

    for (int t = 0; t < SEQL; t++) {
        // prefetch xp for this step before waiting on producers (kq0 warps)
        float2 xv[16];
        if (kq == 0) {
            const float* xpt = xp + (size_t)t * BATCH * GATES;
#pragma unroll
            for (int gi = 0; gi < 4; gi++)
#pragma unroll
                for (int mi = 0; mi < 2; mi++)
#pragma unroll
                    for (int ri = 0; ri < 2; ri++) {
                        int b = bhh * 32 + mi * 16 + ri * 8 + g;
                        xv[gi*4 + mi*2 + ri] =
                            *(const float2*)(xpt + (size_t)b * GATES + gi * 1024 + j0 + 2 * tig);
                    }
        }

        float acc[2][4][4];
#pragma unroll
        for (int mi = 0; mi < 2; mi++)
#pragma unroll
            for (int ni = 0; ni < 4; ni++)
#pragma unroll
                for (int r = 0; r < 4; r++) acc[mi][ni][r] = 0.f;

        if (t > 0) {
            // producer wait: bhh==0 warp polls global, mirrors to smem
            if (bhh == 0) {
                while (*myflag < (unsigned)t) { __nanosleep(40); }
                __syncwarp();
                asm volatile("fence.acq_rel.gpu;" ::: "memory");
                if (lane == 0) sfl[kq * 8] = (unsigned)t;
                __syncwarp();
            } else {
                while (sfl[kq * 8] < (unsigned)t) { __nanosleep(40); }
                asm volatile("fence.acq_rel.gpu;" ::: "memory");
            }
            __syncwarp();

            const float* hp = (mode == 0) ? hist + (size_t)(t-1) * BH
                                          : hist + (size_t)((t-1) & 1) * BH;
            const float* src = hp + (size_t)(bhh * 32 + lane) * 1024 + khb;

            // prologue: stage chunk (rot) into buf0
            {
                const float* s = src + rot * 16;
#pragma unroll
                for (int i = 0; i < 4; i++) cpa16(sdst0 + 16 * i, s + 4 * i);
                CP_COMMIT();
            }

            for (int kc = 0; kc < NCH; kc++) {
                if (kc < NCH - 1) {
                    uint32_t d = ((kc + 1) & 1) ? sdst1 : sdst0;
                    const float* s = src + (((kc + 1 + rot) & 15)) * 16;
#pragma unroll
                    for (int i = 0; i < 4; i++) cpa16(d + 16 * i, s + 4 * i);
                    CP_COMMIT();
                    CP_WAIT(1);
                } else {
                    CP_WAIT(0);
                }
                __syncwarp();
                const float* hb = (kc & 1) ? buf1 : buf0;
                const int kg = khb + ((kc + rot) & 15) * 16;
#pragma unroll
                for (int kk = 0; kk < 2; kk++) {
                    int kloc = kk * 8 + tig;
                    uint32_t a[2][4];
#pragma unroll
                    for (int mi = 0; mi < 2; mi++) {
                        int rb = (mi * 16 + g) * HPAD;
                        a[mi][0] = __float_as_uint(hb[rb + kloc]);
                        a[mi][1] = __float_as_uint(hb[rb + 8 * HPAD + kloc]);
                        a[mi][2] = __float_as_uint(hb[rb + kloc + 4]);
                        a[mi][3] = __float_as_uint(hb[rb + 8 * HPAD + kloc + 4]);
                    }
                    uint4 blo = *(const uint4*)&ws2[(kg + kloc) * PW2 + g * 4];
                    uint4 bhi = *(const uint4*)&ws2[(kg + kloc + 4) * PW2 + g * 4];
                    const uint32_t* bl = (const uint32_t*)&blo;
                    const uint32_t* bu = (const uint32_t*)&bhi;
#pragma unroll
                    for (int mi = 0; mi < 2; mi++)
#pragma unroll
                        for (int ni = 0; ni < 4; ni++) {
                            uint32_t b2[2] = { bl[ni], bu[ni] };
                            mma8(acc[mi][ni], a[mi], b2);
                        }
                }
                __syncwarp();
            }
            // reduction: kq 1-3 -> smem, kq 0 accumulates (per batch half)
            if (kq != 0) {
                float* r = red + ((kq - 1) * 2 + bhh) * 1024 + lane;
#pragma unroll
                for (int mi = 0; mi < 2; mi++)
#pragma unroll
                    for (int ni = 0; ni < 4; ni++)
#pragma unroll
                        for (int q = 0; q < 4; q++)
                            r[(mi * 16 + ni * 4 + q) * 32] = acc[mi][ni][q];
            }
            __syncthreads();
            if (kq == 0) {
#pragma unroll
                for (int p = 0; p < 3; p++) {
                    const float* r = red + (p * 2 + bhh) * 1024 + lane;
#pragma unroll
                    for (int mi = 0; mi < 2; mi++)
#pragma unroll
                        for (int ni = 0; ni < 4; ni++)
#pragma unroll
                            for (int q = 0; q < 4; q++)
                                acc[mi][ni][q] += r[(mi * 16 + ni * 4 + q) * 32];
                }
            }
        }

        if (kq == 0) {
            float* hw = (mode == 0) ? hist + (size_t)t * BH
                                    : hist + (size_t)(t & 1) * BH;
#pragma unroll
            for (int mi = 0; mi < 2; mi++)
#pragma unroll
                for (int ri = 0; ri < 2; ri++)
#pragma unroll
                    for (int ci = 0; ci < 2; ci++) {
                        int q = ri * 2 + ci;
                        int ix = mi * 4 + q;
                        int b = bhh * 32 + mi * 16 + ri * 8 + g;
                        int jj = 2 * tig + ci;
                        float xi = ci ? xv[0*4+mi*2+ri].y : xv[0*4+mi*2+ri].x;
                        float xf = ci ? xv[1*4+mi*2+ri].y : xv[1*4+mi*2+ri].x;
                        float xg = ci ? xv[2*4+mi*2+ri].y : xv[2*4+mi*2+ri].x;
                        float xo = ci ? xv[3*4+mi*2+ri].y : xv[3*4+mi*2+ri].x;
                        float ii = sigf(acc[mi][0][q] + xi);
                        float ff = sigf(acc[mi][1][q] + xf);
                        float gg = tanhfast(acc[mi][2][q] + xg);
                        float oo = sigf(acc[mi][3][q] + xo);
                        float cn = ff * cst[ix] + ii * gg;
                        float hn = oo * tanhfast(cn);
                        cst[ix] = cn;
                        hw[(size_t)b * HID + j0 + jj] = hn;
                        if (t == SEQL - 1) {
                            out_h[(size_t)b * HID + j0 + jj] = hn;
                            out_c[(size_t)b * HID + j0 + jj] = cn;
                        }
                    }
            // EARLY publish: kq0 warps (warps 0 and 4, 64 threads) rendezvous
            // after their h writes, then publish before the block-wide sync.
            __threadfence();
            asm volatile("bar.sync 1, 64;" ::: "memory");
            if (tid == 0) atomicExch((unsigned*)&g_flag[blockIdx.x * 32], (unsigned)(t + 1));
        }
        // end-of-step rendezvous (orders red reuse for next step)
        __syncthreads();
    }
}

// ---------------- launch ----------------------------------------------------
extern "C" void kernel_launch(void* const* d_in, const int* in_sizes, int n_in,
                              void* d_out, int out_size)
{
    const int*   seq  = (const int*)d_in[0];
    const float* emb  = (const float*)d_in[1];
    const float* wih0 = (const float*)d_in[2];
    const float* whh0 = (const float*)d_in[3];
    const float* bih0 = (const float*)d_in[4];
    const float* bhh0 = (const float*)d_in[5];
    const float* wih1 = (const float*)d_in[6];
    const float* whh1 = (const float*)d_in[7];
    const float* bih1 = (const float*)d_in[8];
    const float* bhh1 = (const float*)d_in[9];
    float* out = (float*)d_out;

    float *xp, *ys, *hb;
    cudaGetSymbolAddress((void**)&xp, g_xp);
    cudaGetSymbolAddress((void**)&ys, g_ys);
    cudaGetSymbolAddress((void**)&hb, g_hb);

    cudaFuncSetAttribute(sgemm_xp, cudaFuncAttributeMaxDynamicSharedMemorySize, SGEMM_SMEM);
    cudaFuncSetAttribute(lstm_rec, cudaFuncAttributeMaxDynamicSharedMemorySize, REC_SMEM);

    dim3 gg(GATES / 128, MROWS / 128);   // (32, 128)

    // out layout: [h0 | h1 | c0 | c1], each 64x1024
    sgemm_xp<<<gg, 256, SGEMM_SMEM>>>(emb, seq, wih0, bih0, bhh0, xp);
    lstm_rec<<<128, 256, REC_SMEM>>>(xp, whh0, ys, 0, out, out + 2 * BH);

    sgemm_xp<<<gg, 256, SGEMM_SMEM>>>(ys, nullptr, wih1, bih1, bhh1, xp);
    lstm_rec<<<128, 256, REC_SMEM>>>(xp, whh1, hb, 1, out + BH, out + 3 * BH);
}

// round 17
// speedup vs baseline: 1.3467x; 1.3467x over previous
#include <cuda_runtime.h>
#include <math.h>
#include <stdint.h>

#define SEQL 256
#define BATCH 64
#define HID 1024
#define GATES 4096
#define MROWS (SEQL*BATCH)      // 16384
#define BH (BATCH*HID)          // 65536

// ---------------- scratch (device globals; no cudaMalloc allowed) ----------
__device__ float g_xp[2][(size_t)MROWS * GATES]; // x-projection per layer
__device__ float g_ys[(size_t)SEQL * BH];        // layer-0 h history
__device__ float g_hb[2 * BH];                   // layer-1 h ping-pong
__device__ unsigned g_flag[2][128 * 32];         // per-layer, per-block step flags
__device__ unsigned g_xpcnt[2][128];             // per-layer, per-mtile n-tile counters

// ---------------- helpers ---------------------------------------------------
__device__ __forceinline__ uint32_t f2tf32(float x) {
    uint32_t r; asm("cvt.rna.tf32.f32 %0, %1;" : "=r"(r) : "f"(x)); return r;
}
__device__ __forceinline__ void mma8(float* d, const uint32_t* a, const uint32_t* b) {
    asm volatile(
        "mma.sync.aligned.m16n8k8.row.col.f32.tf32.tf32.f32 "
        "{%0,%1,%2,%3},{%4,%5,%6,%7},{%8,%9},{%0,%1,%2,%3};"
        : "+f"(d[0]), "+f"(d[1]), "+f"(d[2]), "+f"(d[3])
        : "r"(a[0]), "r"(a[1]), "r"(a[2]), "r"(a[3]), "r"(b[0]), "r"(b[1]));
}
__device__ __forceinline__ void cpa16(uint32_t s, const void* g) {
    asm volatile("cp.async.cg.shared.global [%0], [%1], 16;" :: "r"(s), "l"(g));
}
#define CP_COMMIT() asm volatile("cp.async.commit_group;")
#define CP_WAIT(n)  asm volatile("cp.async.wait_group %0;" :: "n"(n))

__device__ __forceinline__ float sigf(float x) { return __fdividef(1.f, 1.f + __expf(-x)); }
__device__ __forceinline__ float tanhfast(float x) { return __fdividef(2.f, 1.f + __expf(-2.f * x)) - 1.f; }

// ---------------- tf32 SGEMM: cp.async 2-stage pipelined ---------------------
// R15 internals + (a) optional wait on producer flags before touching A,
// (b) per-mtile completion counter publish, (c) PDL trigger at start.
#define STG 8192   // floats per stage (As 4096 + Ws 4096)
__global__ __launch_bounds__(256, 2) void sgemm_xp(
    const float* __restrict__ A, const int* __restrict__ gidx,
    const float* __restrict__ W,
    const float* __restrict__ b1, const float* __restrict__ b2,
    float* __restrict__ C,
    unsigned* done_cnt, const unsigned* src_flag)
{
#if __CUDA_ARCH__ >= 900
    cudaTriggerProgrammaticLaunchCompletion();
#endif
    extern __shared__ float smf[];
    const uint32_t smem_b = (uint32_t)__cvta_generic_to_shared(smf);
    const int bn = blockIdx.x * 128;
    const int bm = blockIdx.y * 128;
    const int tid = threadIdx.x;
    const int warp = tid >> 5, lane = tid & 31;
    const int g = lane >> 2, tig = lane & 3;
    const int wm = warp >> 2, wn = warp & 3;

    // wait for A rows (= ys timesteps bm/64, bm/64+1) to be published
    if (src_flag) {
        if (tid < 128) {
            const volatile unsigned* f = (const volatile unsigned*)&src_flag[tid * 32];
            unsigned need = (unsigned)(bm / 64 + 2);
            while (*f < need) { __nanosleep(100); }
        }
        __syncthreads();
        asm volatile("fence.acq_rel.gpu;" ::: "memory");
    }

    int cm[4]; int cj[4]; int arow[4]; uint32_t adst[4], wdst[4];
#pragma unroll
    for (int rep = 0; rep < 4; rep++) {
        int q = tid + rep * 256;
        int m = q >> 3, j = q & 7;
        cm[rep] = m; cj[rep] = j;
        arow[rep] = gidx ? gidx[bm + m] : (bm + m);
        uint32_t off = (uint32_t)(m * 32 + ((4 * j) ^ ((m & 7) << 2)));
        adst[rep] = smem_b + off * 4;
        wdst[rep] = smem_b + (off + 4096) * 4;
    }

    float acc[4][4][4];
#pragma unroll
    for (int mi = 0; mi < 4; mi++)
#pragma unroll
        for (int ni = 0; ni < 4; ni++)
#pragma unroll
            for (int r = 0; r < 4; r++) acc[mi][ni][r] = 0.f;

#pragma unroll
    for (int rep = 0; rep < 4; rep++) {
        cpa16(adst[rep], A + (size_t)arow[rep] * 1024 + 4 * cj[rep]);
        cpa16(wdst[rep], W + (size_t)(bn + cm[rep]) * 1024 + 4 * cj[rep]);
    }
    CP_COMMIT();

    const int swz = g << 2;
    for (int c = 0; c < 32; c++) {
        if (c + 1 < 32) {
            uint32_t so = (uint32_t)(((c + 1) & 1) * STG) * 4;
            int kc = (c + 1) * 32;
#pragma unroll
            for (int rep = 0; rep < 4; rep++) {
                cpa16(adst[rep] + so, A + (size_t)arow[rep] * 1024 + kc + 4 * cj[rep]);
                cpa16(wdst[rep] + so, W + (size_t)(bn + cm[rep]) * 1024 + kc + 4 * cj[rep]);
            }
        }
        CP_COMMIT();
        CP_WAIT(1);
        __syncthreads();

        const float* As = smf + (c & 1) * STG;
        const float* Ws = As + 4096;
#pragma unroll
        for (int kk = 0; kk < 4; kk++) {
            int kl = (kk * 8 + tig) ^ swz;
            int kh = (kk * 8 + tig + 4) ^ swz;
            uint32_t a[4][4], b[4][2];
#pragma unroll
            for (int mi = 0; mi < 4; mi++) {
                int base = (wm * 64 + mi * 16 + g) * 32;
                a[mi][0] = f2tf32(As[base + kl]);
                a[mi][1] = f2tf32(As[base + 256 + kl]);
                a[mi][2] = f2tf32(As[base + kh]);
                a[mi][3] = f2tf32(As[base + 256 + kh]);
            }
#pragma unroll
            for (int ni = 0; ni < 4; ni++) {
                int nb = (wn * 32 + ni * 8 + g) * 32;
                b[ni][0] = f2tf32(Ws[nb + kl]);
                b[ni][1] = f2tf32(Ws[nb + kh]);
            }
#pragma unroll
            for (int mi = 0; mi < 4; mi++)
#pragma unroll
                for (int ni = 0; ni < 4; ni++)
                    mma8(acc[mi][ni], a[mi], b[ni]);
        }
        __syncthreads();
    }

#pragma unroll
    for (int ni = 0; ni < 4; ni++) {
        int nc = bn + wn * 32 + ni * 8 + 2 * tig;
        float bia0 = b1[nc] + b2[nc];
        float bia1 = b1[nc + 1] + b2[nc + 1];
#pragma unroll
        for (int mi = 0; mi < 4; mi++) {
            int mr = bm + wm * 64 + mi * 16 + g;
            *(float2*)(C + (size_t)mr * GATES + nc) =
                make_float2(acc[mi][ni][0] + bia0, acc[mi][ni][1] + bia1);
            *(float2*)(C + (size_t)(mr + 8) * GATES + nc) =
                make_float2(acc[mi][ni][2] + bia0, acc[mi][ni][3] + bia1);
        }
    }
    // publish: this (m,n) tile done
    __threadfence();
    __syncthreads();
    if (tid == 0) atomicAdd(&done_cnt[blockIdx.y], 1u);
}
#define SGEMM_SMEM (2 * STG * 4)

// ---------------- persistent LSTM recurrence (EXACT R15 internals) ----------
// Changes vs R15: flags passed per-layer (memset by host), startup gridbar
// removed (plain __syncthreads), xp-tile counter wait before xv prefetch,
// PDL trigger after weight preload.
#define PW2 36
#define HPAD 20
#define NCH 16
#define CH_F (16 * HPAD)                        // 320 floats per chunk buffer
#define HS_OFF  (1024 * PW2)                    // 36864
#define RED_OFF (HS_OFF + 16 * 2 * CH_F)        // 47104
#define SFL_OFF (RED_OFF + 3 * 4 * 32 * 17)     // 53632
#define REC_SMEM ((SFL_OFF + 32) * 4)           // 214,656 B

__global__ __launch_bounds__(512, 1) void lstm_rec(
    const float* __restrict__ xp, const float* __restrict__ whh,
    float* hist, int mode, float* __restrict__ out_h, float* __restrict__ out_c,
    unsigned* flags, const unsigned* xpcnt)
{
    extern __shared__ float sm[];
    uint32_t* ws2 = (uint32_t*)sm;             // [1024][PW2] tf32
    float* red = sm + RED_OFF;                 // [3][4][32][17]
    volatile unsigned* sfl = (volatile unsigned*)(sm + SFL_OFF);  // [4] mirrors x8 pad

    const int tid  = threadIdx.x;
    const int warp = tid >> 5, lane = tid & 31;
    const int g = lane >> 2, tig = lane & 3;
    const int wm = warp & 3;                   // batch group
    const int kq = warp >> 2;                  // k-quarter (256 k each)
    const int j0 = blockIdx.x * 8;
    const int mrow = wm * 16 + g;              // batch rows: mrow, mrow+8
    const int rot = blockIdx.x & 15;           // chunk-order stagger

    if (tid < 4) sfl[tid * 8] = 0u;

    // warp-private double buffer
    float* buf0 = sm + HS_OFF + warp * 2 * CH_F;
    float* buf1 = buf0 + CH_F;
    const uint32_t b0_u32 = (uint32_t)__cvta_generic_to_shared(buf0);
    const uint32_t b1_u32 = b0_u32 + CH_F * 4;

    // staging role: lane = r + 16*s covers row r, k_local [8s, 8s+8): 2 cpa16
    const int sr = lane & 15;
    const int ss = lane >> 4;
    const uint32_t sdst0 = b0_u32 + (sr * HPAD + ss * 8) * 4;
    const uint32_t sdst1 = b1_u32 + (sr * HPAD + ss * 8) * 4;

    // preload weights: ws2[k][c], c = j*4 + gate (512 threads)
    {
        int c   = tid & 31;                    // j = c>>2, gate = c&3
        int kq2 = tid >> 5;                    // 0..15, 64 k each
        int wrow = ((c & 3) << 10) + j0 + (c >> 2);
        const float4* w4 = (const float4*)(whh + (size_t)wrow * 1024);
        for (int k4 = kq2 * 16; k4 < kq2 * 16 + 16; k4++) {
            float4 v = w4[k4];
            int k = 4 * k4;
            ws2[(k+0)*PW2 + c] = f2tf32(v.x);
            ws2[(k+1)*PW2 + c] = f2tf32(v.y);
            ws2[(k+2)*PW2 + c] = f2tf32(v.z);
            ws2[(k+3)*PW2 + c] = f2tf32(v.w);
        }
    }
    __syncthreads();
#if __CUDA_ARCH__ >= 900
    cudaTriggerProgrammaticLaunchCompletion();
#endif

    float cst[4] = {0.f, 0.f, 0.f, 0.f};       // c-state (kq==0 warps only)
    const int khb = kq * 256;
    const volatile unsigned* myflag = (const volatile unsigned*)&flags[(kq * 32 + lane) * 32];

    for (int t = 0; t < SEQL; t++) {
        // wait for this step's xp tile, then prefetch xp (kq0 warps only)
        float2 xv[8];
        if (kq == 0) {
            const volatile unsigned* xc = (const volatile unsigned*)&xpcnt[t >> 1];
            while (*xc < 32u) { __nanosleep(60); }
            asm volatile("fence.acq_rel.gpu;" ::: "memory");
            const float* xpt = xp + (size_t)t * BATCH * GATES;
#pragma unroll
            for (int gi = 0; gi < 4; gi++)
#pragma unroll
                for (int ri = 0; ri < 2; ri++) {
                    int b = mrow + ri * 8;
                    xv[gi*2+ri] = *(const float2*)(xpt + (size_t)b * GATES + gi * 1024 + j0 + 2 * tig);
                }
        }

        float acc[4][4];
#pragma unroll
        for (int ni = 0; ni < 4; ni++)
#pragma unroll
            for (int r = 0; r < 4; r++) acc[ni][r] = 0.f;

        if (t > 0) {
            // producer wait: wm==0 warp polls global flags, mirrors into smem
            if (wm == 0) {
                while (*myflag < (unsigned)t) { __nanosleep(40); }
                __syncwarp();
                asm volatile("fence.acq_rel.gpu;" ::: "memory");
                if (lane == 0) sfl[kq * 8] = (unsigned)t;
                __syncwarp();
            } else {
                while (sfl[kq * 8] < (unsigned)t) { __nanosleep(40); }
                asm volatile("fence.acq_rel.gpu;" ::: "memory");
            }
            __syncwarp();

            const float* hp = (mode == 0) ? hist + (size_t)(t-1) * BH
                                          : hist + (size_t)((t-1) & 1) * BH;
            const float* src = hp + (size_t)(wm * 16 + sr) * 1024 + khb + ss * 8;

            // prologue: stage chunk (rot) into buf0
            {
                const float* s = src + rot * 16;
                cpa16(sdst0,      s);
                cpa16(sdst0 + 16, s + 4);
                CP_COMMIT();
            }

            for (int kc = 0; kc < NCH; kc++) {
                if (kc < NCH - 1) {
                    uint32_t d = ((kc + 1) & 1) ? sdst1 : sdst0;
                    const float* s = src + (((kc + 1 + rot) & 15)) * 16;
                    cpa16(d,      s);
                    cpa16(d + 16, s + 4);
                    CP_COMMIT();
                    CP_WAIT(1);
                } else {
                    CP_WAIT(0);
                }
                __syncwarp();
                const float* hb = (kc & 1) ? buf1 : buf0;
                const int kg = khb + ((kc + rot) & 15) * 16;
#pragma unroll
                for (int kk = 0; kk < 2; kk++) {
                    int kloc = kk * 8 + tig;
                    uint32_t a[4];
                    a[0] = __float_as_uint(hb[g * HPAD + kloc]);
                    a[1] = __float_as_uint(hb[(g + 8) * HPAD + kloc]);
                    a[2] = __float_as_uint(hb[g * HPAD + kloc + 4]);
                    a[3] = __float_as_uint(hb[(g + 8) * HPAD + kloc + 4]);
                    uint4 blo = *(const uint4*)&ws2[(kg + kloc) * PW2 + g * 4];
                    uint4 bhi = *(const uint4*)&ws2[(kg + kloc + 4) * PW2 + g * 4];
                    const uint32_t* bl = (const uint32_t*)&blo;
                    const uint32_t* bh = (const uint32_t*)&bhi;
#pragma unroll
                    for (int ni = 0; ni < 4; ni++) {
                        uint32_t b2[2] = { bl[ni], bh[ni] };
                        mma8(acc[ni], a, b2);
                    }
                }
                __syncwarp();
            }
            // reduction: quarters 1-3 -> smem, quarter 0 accumulates
            if (kq != 0) {
                float* r = red + (kq - 1) * 2176 + (wm * 32 + lane) * 17;
#pragma unroll
                for (int ni = 0; ni < 4; ni++)
#pragma unroll
                    for (int q = 0; q < 4; q++) r[ni * 4 + q] = acc[ni][q];
            }
            __syncthreads();
            if (kq == 0) {
#pragma unroll
                for (int p = 0; p < 3; p++) {
                    const float* r = red + p * 2176 + (wm * 32 + lane) * 17;
#pragma unroll
                    for (int ni = 0; ni < 4; ni++)
#pragma unroll
                        for (int q = 0; q < 4; q++) acc[ni][q] += r[ni * 4 + q];
                }
            }
        }

        if (kq == 0) {
            float* hw = (mode == 0) ? hist + (size_t)t * BH
                                    : hist + (size_t)(t & 1) * BH;
#pragma unroll
            for (int ri = 0; ri < 2; ri++)
#pragma unroll
                for (int ci = 0; ci < 2; ci++) {
                    int r = ri * 2 + ci;
                    int b = mrow + ri * 8;
                    int jj = 2 * tig + ci;
                    float xi = ci ? xv[0*2+ri].y : xv[0*2+ri].x;
                    float xf = ci ? xv[1*2+ri].y : xv[1*2+ri].x;
                    float xg = ci ? xv[2*2+ri].y : xv[2*2+ri].x;
                    float xo = ci ? xv[3*2+ri].y : xv[3*2+ri].x;
                    float ii = sigf(acc[0][r] + xi);
                    float ff = sigf(acc[1][r] + xf);
                    float gg = tanhfast(acc[2][r] + xg);
                    float oo = sigf(acc[3][r] + xo);
                    float cn = ff * cst[r] + ii * gg;
                    float hn = oo * tanhfast(cn);
                    cst[r] = cn;
                    hw[(size_t)b * HID + j0 + jj] = hn;
                    if (t == SEQL - 1) {
                        out_h[(size_t)b * HID + j0 + jj] = hn;
                        out_c[(size_t)b * HID + j0 + jj] = cn;
                    }
                }
            // EARLY publish (R15): kq0 warps rendezvous, then release flag
            __threadfence();
            asm volatile("bar.sync 1, 128;" ::: "memory");
            if (tid == 0) atomicExch(&flags[blockIdx.x * 32], (unsigned)(t + 1));
        }
        __syncthreads();
    }
}

// ---------------- launch ----------------------------------------------------
extern "C" void kernel_launch(void* const* d_in, const int* in_sizes, int n_in,
                              void* d_out, int out_size)
{
    const int*   seq  = (const int*)d_in[0];
    const float* emb  = (const float*)d_in[1];
    const float* wih0 = (const float*)d_in[2];
    const float* whh0 = (const float*)d_in[3];
    const float* bih0 = (const float*)d_in[4];
    const float* bhh0 = (const float*)d_in[5];
    const float* wih1 = (const float*)d_in[6];
    const float* whh1 = (const float*)d_in[7];
    const float* bih1 = (const float*)d_in[8];
    const float* bhh1 = (const float*)d_in[9];
    float* out = (float*)d_out;

    float *xp, *ys, *hb; unsigned *flags, *xpcnt;
    cudaGetSymbolAddress((void**)&xp, g_xp);
    cudaGetSymbolAddress((void**)&ys, g_ys);
    cudaGetSymbolAddress((void**)&hb, g_hb);
    cudaGetSymbolAddress((void**)&flags, g_flag);
    cudaGetSymbolAddress((void**)&xpcnt, g_xpcnt);
    float* xp0 = xp;
    float* xp1 = xp + (size_t)MROWS * GATES;
    unsigned* flag0 = flags;
    unsigned* flag1 = flags + 128 * 32;
    unsigned* cnt0 = xpcnt;
    unsigned* cnt1 = xpcnt + 128;

    cudaFuncSetAttribute(sgemm_xp, cudaFuncAttributeMaxDynamicSharedMemorySize, SGEMM_SMEM);
    cudaFuncSetAttribute(lstm_rec, cudaFuncAttributeMaxDynamicSharedMemorySize, REC_SMEM);

    // reset synchronization state (graph-capturable async memsets)
    cudaMemsetAsync(flags, 0, 2 * 128 * 32 * sizeof(unsigned), 0);
    cudaMemsetAsync(xpcnt, 0, 2 * 128 * sizeof(unsigned), 0);

    dim3 gg(GATES / 128, MROWS / 128);   // (32, 128)

    cudaLaunchAttribute pdl[1];
    pdl[0].id = cudaLaunchAttributeProgrammaticStreamSerialization;
    pdl[0].val.programmaticStreamSerializationAllowed = 1;

    cudaLaunchConfig_t cs{};   // sgemm config (no PDL on first)
    cs.gridDim = gg; cs.blockDim = dim3(256, 1, 1);
    cs.dynamicSmemBytes = SGEMM_SMEM; cs.stream = 0;
    cs.attrs = nullptr; cs.numAttrs = 0;

    cudaLaunchConfig_t csp = cs;   // sgemm config with PDL
    csp.attrs = pdl; csp.numAttrs = 1;

    cudaLaunchConfig_t cr{};   // lstm_rec config with PDL
    cr.gridDim = dim3(128, 1, 1); cr.blockDim = dim3(512, 1, 1);
    cr.dynamicSmemBytes = REC_SMEM; cr.stream = 0;
    cr.attrs = pdl; cr.numAttrs = 1;

    // out layout: [h0 | h1 | c0 | c1], each 64x1024
    cudaLaunchKernelEx(&cs,  sgemm_xp, emb, seq, wih0, bih0, bhh0, xp0,
                       cnt0, (const unsigned*)nullptr);
    cudaLaunchKernelEx(&cr,  lstm_rec, (const float*)xp0, whh0, ys, 0,
                       out, out + 2 * BH, flag0, (const unsigned*)cnt0);
    cudaLaunchKernelEx(&csp, sgemm_xp, (const float*)ys, (const int*)nullptr,
                       wih1, bih1, bhh1, xp1, cnt1, (const unsigned*)flag0);
    cudaLaunchKernelEx(&cr,  lstm_rec, (const float*)xp1, whh1, hb, 1,
                       out + BH, out + 3 * BH, flag1, (const unsigned*)cnt1);
}